// round 16
// baseline (speedup 1.0000x reference)
#include <cuda_runtime.h>

#define BB 2
#define FF 32
#define NN 1024
#define HH 64
#define TI 32
#define TJ 64

// Scratch: [b][hslot][n], hslot 0..63 = Hi (with b1 folded in), 64..127 = Hj
__device__ float g_H[BB * 128 * NN];

__device__ __forceinline__ float sigmoidf_fast(float x) {
    return __fdividef(1.0f, 1.0f + __expf(-x));
}

// packed step: acc2 += max(hid2 + hj2, 0) * w2   (element-wise on f32x2)
#define EDGE_STEP(ACC, HID, HJ2, W2)                                   \
    asm("{\n\t"                                                        \
        ".reg .b64 s;\n\t"                                             \
        ".reg .f32 sl, sh;\n\t"                                        \
        "add.rn.f32x2 s, %1, %2;\n\t"                                  \
        "mov.b64 {sl, sh}, s;\n\t"                                     \
        "max.f32 sl, sl, 0f00000000;\n\t"                              \
        "max.f32 sh, sh, 0f00000000;\n\t"                              \
        "mov.b64 s, {sl, sh};\n\t"                                     \
        "fma.rn.f32x2 %0, s, %3, %0;\n\t"                              \
        "}" : "+l"(ACC) : "l"(HID), "l"(HJ2), "l"(W2))

#define DUP2(D, S)                                                     \
    asm("mov.b64 %0, {%1, %1};" : "=l"(D) : "f"(S))

#define UNPACK2(LO, HI, S)                                             \
    asm("mov.b64 {%0, %1}, %2;" : "=f"(LO), "=f"(HI) : "l"(S))

// ---------------------------------------------------------------------------
// Phase 1: Hi[b,h,n] = sum_f emb[b,f,n]*W1[h,f] + b1[h]
//          Hj[b,h,n] = sum_f emb[b,f,n]*W1[h,F+f]
// ---------------------------------------------------------------------------
__global__ void __launch_bounds__(128) phase1_kernel(
    const float* __restrict__ emb,  // [B][F][N]
    const float* __restrict__ W1,   // [H][2F]
    const float* __restrict__ b1)   // [H]
{
    const int t   = threadIdx.x;        // 0..127 = hslot
    const int h   = t & 63;
    const int isj = t >> 6;
    const int blk = blockIdx.x;
    const int b   = blk / (NN / 16);
    const int n0  = (blk % (NN / 16)) * 16;

    __shared__ float es[FF][16];

    {
        int f  = t >> 2;
        int n4 = t & 3;
        *(float4*)&es[f][n4 * 4] =
            *(const float4*)&emb[(b * FF + f) * NN + n0 + n4 * 4];
    }

    float w[FF];
    #pragma unroll
    for (int f = 0; f < FF; f++)
        w[f] = W1[h * (2 * FF) + isj * FF + f];
    const float bias = isj ? 0.0f : b1[h];

    __syncthreads();

    float* outp = &g_H[(size_t)(b * 128 + t) * NN + n0];
    #pragma unroll
    for (int n4 = 0; n4 < 4; n4++) {
        float a0 = bias, a1 = bias, a2 = bias, a3 = bias;
        #pragma unroll
        for (int f = 0; f < FF; f++) {
            float4 ev = *(float4*)&es[f][n4 * 4];
            a0 = fmaf(ev.x, w[f], a0);
            a1 = fmaf(ev.y, w[f], a1);
            a2 = fmaf(ev.z, w[f], a2);
            a3 = fmaf(ev.w, w[f], a3);
        }
        float4 r = {a0, a1, a2, a3};
        *(float4*)&outp[n4 * 4] = r;
    }
}

// ---------------------------------------------------------------------------
// Phase 2: out[b,i,j] = sigmoid( sum_h relu(Hi[b,i,h]+Hj[b,j,h]) * W2[h] + b2 )
// 32x64 (i,j) tile per block, 256 threads, 2i x 4j per thread.
// Hi stored in smem PRE-DUPLICATED as (hi,hi) f32x2 pairs, so the inner loop
// is 3 LDS + 16 packed-math per h per thread with no pack MOVs.
// ---------------------------------------------------------------------------
__global__ void __launch_bounds__(256, 6) phase2_kernel(
    const float* __restrict__ W2,   // [1][H]
    const float* __restrict__ b2,   // [1]
    float* __restrict__ out)        // [B][N][N]
{
    __shared__ __align__(16) unsigned long long his[HH * TI];  // dup'd pairs, 16KB
    __shared__ __align__(16) float hjs[HH * TJ];               // 16KB
    __shared__ unsigned long long w2d[HH];                     // dup'd w, 512B

    const int tid = threadIdx.x;
    const int b   = blockIdx.z;
    const int i0  = blockIdx.y * TI;
    const int j0  = blockIdx.x * TJ;
    const int tx  = tid & 15;   // 4 j's (2 packed pairs)
    const int ty  = tid >> 4;   // 2 i's

    const float* HiB = &g_H[(size_t)(b * 128) * NN];
    const float* HjB = &g_H[(size_t)(b * 128 + 64) * NN];

    // his: 64h x 32i floats -> dup'd pairs. 512 float4 / 256 thr = 2 each.
    #pragma unroll
    for (int k = 0; k < 2; k++) {
        int idx = tid + k * 256;
        int hh  = idx >> 3;
        int i4  = (idx & 7) * 4;
        float4 v = *(const float4*)&HiB[hh * NN + i0 + i4];
        unsigned long long d0, d1, d2, d3;
        DUP2(d0, v.x); DUP2(d1, v.y); DUP2(d2, v.z); DUP2(d3, v.w);
        ulonglong2 p0 = {d0, d1};
        ulonglong2 p1 = {d2, d3};
        *(ulonglong2*)&his[hh * TI + i4]     = p0;
        *(ulonglong2*)&his[hh * TI + i4 + 2] = p1;
    }
    // hjs: 64h x 64j floats = 1024 float4 / 256 thr = 4 each.
    #pragma unroll
    for (int k = 0; k < 4; k++) {
        int idx = tid + k * 256;
        int hh  = idx >> 4;
        int j4  = (idx & 15) * 4;
        *(float4*)&hjs[hh * TJ + j4] = *(const float4*)&HjB[hh * NN + j0 + j4];
    }
    if (tid < HH) {
        unsigned long long wp;
        DUP2(wp, W2[tid]);
        w2d[tid] = wp;
    }
    __syncthreads();

    unsigned long long acc[2][2] = {0ull, 0ull, 0ull, 0ull};

    const unsigned long long* hip = &his[ty * 2];
    const float*              hjp = &hjs[tx * 4];

    #pragma unroll 16
    for (int h = 0; h < HH; h++) {
        ulonglong2 hi = *(const ulonglong2*)&hip[h * TI];  // LDS.128: dup(i0), dup(i0+1)
        ulonglong2 hj = *(const ulonglong2*)&hjp[h * TJ];  // LDS.128: (j0,j1),(j2,j3)
        unsigned long long w = w2d[h];                     // LDS.64 broadcast

        EDGE_STEP(acc[0][0], hi.x, hj.x, w);
        EDGE_STEP(acc[0][1], hi.x, hj.y, w);
        EDGE_STEP(acc[1][0], hi.y, hj.x, w);
        EDGE_STEP(acc[1][1], hi.y, hj.y, w);
    }

    const float b2v = b2[0];
    #pragma unroll
    for (int r = 0; r < 2; r++) {
        float a0, a1, a2, a3;
        UNPACK2(a0, a1, acc[r][0]);
        UNPACK2(a2, a3, acc[r][1]);
        float4 o;
        o.x = sigmoidf_fast(a0 + b2v);
        o.y = sigmoidf_fast(a1 + b2v);
        o.z = sigmoidf_fast(a2 + b2v);
        o.w = sigmoidf_fast(a3 + b2v);
        size_t row = (size_t)(b * NN + i0 + ty * 2 + r) * NN;
        *(float4*)&out[row + j0 + tx * 4] = o;
    }
}

// ---------------------------------------------------------------------------
// inputs (metadata order): 0=adj_in (unused), 1=emb_in, 2=layer (unused),
//                          3=W1, 4=b1, 5=W2, 6=b2
// ---------------------------------------------------------------------------
extern "C" void kernel_launch(void* const* d_in, const int* in_sizes, int n_in,
                              void* d_out, int out_size)
{
    const float* emb = (const float*)d_in[1];
    const float* W1  = (const float*)d_in[3];
    const float* b1  = (const float*)d_in[4];
    const float* W2  = (const float*)d_in[5];
    const float* b2  = (const float*)d_in[6];
    float* out = (float*)d_out;

    phase1_kernel<<<BB * (NN / 16), 128>>>(emb, W1, b1);

    dim3 grid(NN / TJ, NN / TI, BB);
    phase2_kernel<<<grid, 256>>>(W2, b2, out);
}